// round 5
// baseline (speedup 1.0000x reference)
#include <cuda_runtime.h>
#include <stdint.h>

#define T_DIM 8
#define C_DIM 4
#define H_DIM 1024
#define W_DIM 1024
#define NIMG  (T_DIM * C_DIM)
#define NGRID 16
#define NCELLS (NGRID * NGRID)
#define THRESH 0.65f
#define NUM_FG 40
#define NUM_BG 1
#define MAX_PTS 42

// Scratch (allocation-free rule: __device__ globals)
__device__ unsigned long long g_cell[NIMG * NCELLS];  // per-cell fg best: (score_bits<<32)|~flat_idx, 0 = no fg
__device__ unsigned long long g_max[NIMG];            // global argmax: (score_bits<<32)|~flat_idx  (atomicMax)
__device__ unsigned long long g_min[NIMG];            // global argmin: (score_bits<<32)| flat_idx  (atomicMin)

static __device__ __forceinline__ unsigned long long umaxll(unsigned long long a, unsigned long long b){ return a > b ? a : b; }
static __device__ __forceinline__ unsigned long long uminll(unsigned long long a, unsigned long long b){ return a < b ? a : b; }

__global__ void init_kernel() {
    int i = threadIdx.x;
    if (i < NIMG) { g_max[i] = 0ULL; g_min[i] = ~0ULL; }
}

// One block per (image, cell). 256 threads, each loads 4 float4 (64x64 cell = 1024 float4).
__global__ void __launch_bounds__(256) cell_kernel(const float* __restrict__ sim) {
    int blk  = blockIdx.x;
    int img  = blk >> 8;
    int cell = blk & 255;
    int cy = cell >> 4, cx = cell & 15;
    const float4* base = (const float4*)(sim + (size_t)img * H_DIM * W_DIM);
    const int ROW_F4 = W_DIM / 4;  // 256

    unsigned long long fgBest = 0ULL;
    unsigned long long aMax   = 0ULL;
    unsigned long long aMin   = ~0ULL;

    int tid = threadIdx.x;
#pragma unroll
    for (int it = 0; it < 4; it++) {
        int f   = tid + it * 256;       // 0..1023
        int r   = f >> 4;               // 0..63 row within cell
        int c4  = f & 15;               // 0..15 float4 within cell row
        int row = cy * 64 + r;
        int col4 = cx * 16 + c4;
        float4 v = base[row * ROW_F4 + col4];
        unsigned idx0 = (unsigned)(row * W_DIM + col4 * 4);
        float vals[4] = {v.x, v.y, v.z, v.w};
#pragma unroll
        for (int k = 0; k < 4; k++) {
            unsigned idx = idx0 + k;
            unsigned long long pm = ((unsigned long long)__float_as_uint(vals[k]) << 32) | (unsigned)(~idx);
            unsigned long long pn = ((unsigned long long)__float_as_uint(vals[k]) << 32) | idx;
            aMax = umaxll(aMax, pm);
            aMin = uminll(aMin, pn);
            if (vals[k] > THRESH) fgBest = umaxll(fgBest, pm);
        }
    }
    // warp reduce
#pragma unroll
    for (int off = 16; off; off >>= 1) {
        fgBest = umaxll(fgBest, __shfl_xor_sync(0xffffffffu, fgBest, off));
        aMax   = umaxll(aMax,   __shfl_xor_sync(0xffffffffu, aMax,   off));
        aMin   = uminll(aMin,   __shfl_xor_sync(0xffffffffu, aMin,   off));
    }
    __shared__ unsigned long long sF[8], sA[8], sM[8];
    int w = tid >> 5, lane = tid & 31;
    if (lane == 0) { sF[w] = fgBest; sA[w] = aMax; sM[w] = aMin; }
    __syncthreads();
    if (tid == 0) {
#pragma unroll
        for (int i = 1; i < 8; i++) {
            fgBest = umaxll(fgBest, sF[i]);
            aMax   = umaxll(aMax,   sA[i]);
            aMin   = uminll(aMin,   sM[i]);
        }
        g_cell[blk] = fgBest;
        atomicMax(&g_max[img], aMax);
        atomicMin(&g_min[img], aMin);
    }
}

// One block per image. Thread t owns cell t. Rank via O(256^2) shared compares.
__global__ void __launch_bounds__(256) final_kernel(const int* __restrict__ ori,
                                                    float* __restrict__ out,
                                                    int write_nums) {
    int img = blockIdx.x;
    int t   = img / C_DIM;
    int tid = threadIdx.x;

    float sx = (float)ori[t * 2 + 1] / (float)W_DIM;
    float sy = (float)ori[t * 2 + 0] / (float)H_DIM;

    __shared__ unsigned long long key[NCELLS];

    unsigned long long packed = g_cell[img * NCELLS + tid];
    bool valid = (packed != 0ULL);
    unsigned bits = (unsigned)(packed >> 32);
    unsigned pidx = ~(unsigned)(packed & 0xFFFFFFFFULL);

    // Unique sort key: descending score, then ascending cell id; invalid cells last (stable by cid).
    unsigned long long k = valid ? ((packed & 0xFFFFFFFF00000000ULL) | (unsigned)(255 - tid))
                                 : (unsigned long long)(unsigned)(255 - tid);
    key[tid] = k;
    int nvalid = __syncthreads_count((int)valid);

    int rank = 0;
#pragma unroll 8
    for (int j = 0; j < NCELLS; j++) rank += (key[j] > k) ? 1 : 0;

    bool any_fg  = (nvalid > 0);
    int fg_count = any_fg ? (nvalid < NUM_FG ? nvalid : NUM_FG) : 1;

    float* o = out + (size_t)img * MAX_PTS * 4;
    if (tid < MAX_PTS * 4) o[tid] = 0.0f;   // 168 < 256, full zero of this image's block
    __syncthreads();

    if (any_fg) {
        if (rank < NUM_FG && valid) {
            float s  = __uint_as_float(bits);
            float px = (float)(pidx % W_DIM);
            float py = (float)(pidx / W_DIM);
            float* r = o + rank * 4;
            r[0] = px * sx; r[1] = py * sy; r[2] = s; r[3] = 1.0f;
        }
    } else if (tid == 0) {
        unsigned long long pm = g_max[img];
        unsigned gb = (unsigned)(pm >> 32);
        unsigned gi = ~(unsigned)(pm & 0xFFFFFFFFULL);
        o[0] = (float)(gi % W_DIM) * sx;
        o[1] = (float)(gi / W_DIM) * sy;
        o[2] = __uint_as_float(gb);
        o[3] = 1.0f;
    }

    if (tid == 0) {
        unsigned long long pn = g_min[img];
        unsigned bb = (unsigned)(pn >> 32);
        unsigned bi = (unsigned)(pn & 0xFFFFFFFFULL);
        float* r = o + fg_count * 4;
        r[0] = (float)(bi % W_DIM) * sx;
        r[1] = (float)(bi / W_DIM) * sy;
        r[2] = __uint_as_float(bb);
        r[3] = 0.0f;
        if (write_nums) {
            float* nums = out + (size_t)NIMG * MAX_PTS * 4;
            nums[img] = (float)(fg_count + NUM_BG);
        }
    }
}

extern "C" void kernel_launch(void* const* d_in, const int* in_sizes, int n_in,
                              void* d_out, int out_size) {
    const float* sim = (const float*)d_in[0];
    // d_in[1] = category_ids (unused by the reference output)
    const int* ori = (const int*)d_in[2];

    init_kernel<<<1, 32>>>();
    cell_kernel<<<NIMG * NCELLS, 256>>>(sim);
    int write_nums = (out_size >= NIMG * MAX_PTS * 4 + NIMG) ? 1 : 0;
    final_kernel<<<NIMG, 256>>>(ori, (float*)d_out, write_nums);
}

// round 6
// speedup vs baseline: 1.2524x; 1.2524x over previous
#include <cuda_runtime.h>
#include <stdint.h>

#define T_DIM 8
#define C_DIM 4
#define H_DIM 1024
#define W_DIM 1024
#define NIMG  (T_DIM * C_DIM)
#define NGRID 16
#define NCELLS (NGRID * NGRID)
#define THRESH 0.65f
#define NUM_FG 40
#define NUM_BG 1
#define MAX_PTS 42

// Scratch (__device__ globals; zero-initialized at module load).
__device__ unsigned long long g_cmax[NIMG * NCELLS]; // (score_bits<<32) | ~flat_idx  (max, min-idx tie-break)
__device__ unsigned long long g_cmin[NIMG * NCELLS]; // (score_bits<<32) |  flat_idx  (min, min-idx tie-break)
__device__ unsigned int       g_cnt[NIMG];           // arrival counters; always returned to 0 by the last block

static __device__ __forceinline__ unsigned long long umaxll(unsigned long long a, unsigned long long b){ return a > b ? a : b; }
static __device__ __forceinline__ unsigned long long uminll(unsigned long long a, unsigned long long b){ return a < b ? a : b; }

__global__ void __launch_bounds__(256)
fused_kernel(const float* __restrict__ sim,
             const int*   __restrict__ ori,
             float*       __restrict__ out,
             int write_nums)
{
    const int blk  = blockIdx.x;
    const int img  = blk >> 8;
    const int cell = blk & 255;
    const int cy = cell >> 4, cx = cell & 15;
    const int tid = threadIdx.x;
    const float4* base = (const float4*)(sim + (size_t)img * (H_DIM * W_DIM));

    // ---------------- Phase 1: per-cell scan (value-only tracking) ----------------
    float vals[16];
    int   idx0s[4];
    float vmax = -1.0f, vmin = 2.0f;

#pragma unroll
    for (int it = 0; it < 4; it++) {
        int f    = tid + it * 256;          // 0..1023
        int r    = f >> 4;                  // row within cell
        int c4   = f & 15;                  // float4 within cell row
        int row  = cy * 64 + r;
        int col4 = cx * 16 + c4;
        float4 v = __ldcs(&base[row * (W_DIM / 4) + col4]);
        idx0s[it] = row * W_DIM + col4 * 4;
        vals[it * 4 + 0] = v.x; vals[it * 4 + 1] = v.y;
        vals[it * 4 + 2] = v.z; vals[it * 4 + 3] = v.w;
        vmax = fmaxf(vmax, fmaxf(fmaxf(v.x, v.y), fmaxf(v.z, v.w)));
        vmin = fminf(vmin, fminf(fminf(v.x, v.y), fminf(v.z, v.w)));
    }

    // Warp float reductions.
    float wmax = vmax, wmin = vmin;
#pragma unroll
    for (int off = 16; off; off >>= 1) {
        wmax = fmaxf(wmax, __shfl_xor_sync(0xffffffffu, wmax, off));
        wmin = fminf(wmin, __shfl_xor_sync(0xffffffffu, wmin, off));
    }

    // Deferred index resolution: only lanes holding the warp extremum scan
    // their registers. Descending iteration + overwrite keeps the SMALLEST
    // local flat index (matching the reference's first-occurrence semantics).
    unsigned candMaxIdx = 0xffffffffu, candMinIdx = 0xffffffffu;
    if (vmax == wmax) {
#pragma unroll
        for (int it = 3; it >= 0; it--)
#pragma unroll
            for (int k = 3; k >= 0; k--)
                if (vals[it * 4 + k] == wmax) candMaxIdx = (unsigned)(idx0s[it] + k);
    }
    if (vmin == wmin) {
#pragma unroll
        for (int it = 3; it >= 0; it--)
#pragma unroll
            for (int k = 3; k >= 0; k--)
                if (vals[it * 4 + k] == wmin) candMinIdx = (unsigned)(idx0s[it] + k);
    }
#pragma unroll
    for (int off = 16; off; off >>= 1) {
        candMaxIdx = min(candMaxIdx, __shfl_xor_sync(0xffffffffu, candMaxIdx, off));
        candMinIdx = min(candMinIdx, __shfl_xor_sync(0xffffffffu, candMinIdx, off));
    }

    // Cross-warp reduce with exact tie-break via packing (scores are in [0,1),
    // so float bit patterns order monotonically).
    __shared__ unsigned long long sMax[8], sMin[8];
    const int w = tid >> 5, lane = tid & 31;
    if (lane == 0) {
        sMax[w] = ((unsigned long long)__float_as_uint(wmax) << 32) | (unsigned)(~candMaxIdx);
        sMin[w] = ((unsigned long long)__float_as_uint(wmin) << 32) | candMinIdx;
    }
    __syncthreads();

    __shared__ int sLast;
    if (tid == 0) {
        unsigned long long m = sMax[0], n = sMin[0];
#pragma unroll
        for (int i = 1; i < 8; i++) { m = umaxll(m, sMax[i]); n = uminll(n, sMin[i]); }
        g_cmax[blk] = m;
        g_cmin[blk] = n;
        __threadfence();                       // make cell results visible
        unsigned prev = atomicAdd(&g_cnt[img], 1u);
        int last = (prev == NCELLS - 1);
        if (last) g_cnt[img] = 0;              // self-reset for next graph replay
        sLast = last;
    }
    __syncthreads();
    if (!sLast) return;

    // ---------------- Phase 2: finalize (one block per image survives) ----------------
    __threadfence();                           // acquire side of the handoff

    const int t = img / C_DIM;
    const float sx = (float)ori[t * 2 + 1] / (float)W_DIM;
    const float sy = (float)ori[t * 2 + 0] / (float)H_DIM;

    __shared__ unsigned long long key[NCELLS];
    __shared__ unsigned long long sG[16];      // [0:8) img-max partials, [8:16) img-min partials

    unsigned long long pM = g_cmax[img * NCELLS + tid];
    unsigned long long pN = g_cmin[img * NCELLS + tid];
    unsigned bits = (unsigned)(pM >> 32);
    unsigned pidx = ~(unsigned)(pM & 0xffffffffull);
    bool valid = __uint_as_float(bits) > THRESH;   // fg cell iff cell max exceeds threshold

    // Unique sort key: descending score, ascending cell id; invalid cells last (stable by cid).
    unsigned long long k = valid ? ((pM & 0xFFFFFFFF00000000ULL) | (unsigned)(255 - tid))
                                 : (unsigned long long)(unsigned)(255 - tid);
    key[tid] = k;

    // Image-global extrema (replaces the old atomics + init kernel).
    unsigned long long gm = pM, gn = pN;
#pragma unroll
    for (int off = 16; off; off >>= 1) {
        gm = umaxll(gm, __shfl_xor_sync(0xffffffffu, gm, off));
        gn = uminll(gn, __shfl_xor_sync(0xffffffffu, gn, off));
    }
    if (lane == 0) { sG[w] = gm; sG[8 + w] = gn; }

    int nvalid = __syncthreads_count((int)valid);

    int rank = 0;
#pragma unroll 8
    for (int j = 0; j < NCELLS; j++) rank += (key[j] > k) ? 1 : 0;

    bool any_fg  = (nvalid > 0);
    int fg_count = any_fg ? (nvalid < NUM_FG ? nvalid : NUM_FG) : 1;

    float* o = out + (size_t)img * MAX_PTS * 4;
    if (tid < MAX_PTS * 4) o[tid] = 0.0f;      // 168 < 256: full zero of this image's block
    __syncthreads();

    if (any_fg) {
        if (rank < NUM_FG && valid) {
            float s  = __uint_as_float(bits);
            float px = (float)(pidx % W_DIM);
            float py = (float)(pidx / W_DIM);
            float* r = o + rank * 4;
            r[0] = px * sx; r[1] = py * sy; r[2] = s; r[3] = 1.0f;
        }
    } else if (tid == 0) {
        unsigned long long m = sG[0];
#pragma unroll
        for (int i = 1; i < 8; i++) m = umaxll(m, sG[i]);
        unsigned gb = (unsigned)(m >> 32);
        unsigned gi = ~(unsigned)(m & 0xffffffffull);
        o[0] = (float)(gi % W_DIM) * sx;
        o[1] = (float)(gi / W_DIM) * sy;
        o[2] = __uint_as_float(gb);
        o[3] = 1.0f;
    }

    if (tid == 0) {
        unsigned long long n = sG[8];
#pragma unroll
        for (int i = 1; i < 8; i++) n = uminll(n, sG[8 + i]);
        unsigned bb = (unsigned)(n >> 32);
        unsigned bi = (unsigned)(n & 0xffffffffull);
        float* r = o + fg_count * 4;
        r[0] = (float)(bi % W_DIM) * sx;
        r[1] = (float)(bi / W_DIM) * sy;
        r[2] = __uint_as_float(bb);
        r[3] = 0.0f;
        if (write_nums) {
            float* nums = out + (size_t)NIMG * MAX_PTS * 4;
            nums[img] = (float)(fg_count + NUM_BG);
        }
    }
}

extern "C" void kernel_launch(void* const* d_in, const int* in_sizes, int n_in,
                              void* d_out, int out_size) {
    const float* sim = (const float*)d_in[0];
    // d_in[1] = category_ids (unused by the reference output)
    const int* ori = (const int*)d_in[2];

    int write_nums = (out_size >= NIMG * MAX_PTS * 4 + NIMG) ? 1 : 0;
    fused_kernel<<<NIMG * NCELLS, 256>>>(sim, ori, (float*)d_out, write_nums);
}

// round 7
// speedup vs baseline: 1.4398x; 1.1496x over previous
#include <cuda_runtime.h>
#include <stdint.h>

#define T_DIM 8
#define C_DIM 4
#define H_DIM 1024
#define W_DIM 1024
#define NIMG  (T_DIM * C_DIM)
#define NGRID 16
#define NCELLS (NGRID * NGRID)
#define THRESH 0.65f
#define NUM_FG 40
#define NUM_BG 1
#define MAX_PTS 42
#define ROW_F4 (W_DIM / 4)   // 256

// Scratch (__device__ globals). Each cell has exactly ONE writer warp, and the
// written value is a pure function of the inputs -> plain stores are idempotent
// across graph replays (no init kernel, no atomics needed).
__device__ unsigned long long g_cmax[NIMG * NCELLS]; // (score_bits<<32) | ~flat_idx  (max, min-idx tie-break)
__device__ unsigned long long g_cmin[NIMG * NCELLS]; // (score_bits<<32) |  flat_idx  (min, min-idx tie-break)
__device__ unsigned int       g_cnt[NIMG];           // arrival counters; last block resets to 0

static __device__ __forceinline__ unsigned long long umaxll(unsigned long long a, unsigned long long b){ return a > b ? a : b; }
static __device__ __forceinline__ unsigned long long uminll(unsigned long long a, unsigned long long b){ return a < b ? a : b; }

__global__ void __launch_bounds__(256)
fused_kernel(const float* __restrict__ sim,
             const int*   __restrict__ ori,
             float*       __restrict__ out,
             int write_nums)
{
    const int blk = blockIdx.x;            // 0..511
    const int img = blk >> 4;              // 32 images
    const int cy  = blk & 15;              // this block owns cell-row cy (16 cells)
    const int tid  = threadIdx.x;
    const int w    = tid >> 5;             // warp 0..7: owns cells cx = 2w, 2w+1
    const int lane = tid & 31;
    const float4* base = (const float4*)(sim + (size_t)img * (H_DIM * W_DIM));

    // Lane geometry inside a chunk (8 rows x 64 cols of one cell):
    //   it in 0..3 covers row pair (it*2 + rsub); lanes 0-15 / 16-31 each cover
    //   a full 256B row -> every LDG.128 is perfectly coalesced (2 rows x 256B).
    const int rsub = lane >> 4;            // 0..1
    const int csub = lane & 15;            // 0..15

    // q = 0..15 linear chunk id: cell cx = 2w + (q>>3), chunk c = q&7.
    // float4 index of (q, it=0) for this lane:
    #define A0(q) ((cy * 64 + ((q) & 7) * 8 + rsub) * ROW_F4 + (2 * w + ((q) >> 3)) * 16 + csub)

    float4 cur[4], nxt[4];
    {
        const int a = A0(0);
        #pragma unroll
        for (int it = 0; it < 4; it++) cur[it] = __ldcs(base + a + it * (2 * ROW_F4));
    }

    #pragma unroll
    for (int cc = 0; cc < 2; cc++) {       // two cells per warp
        float vmax = -1.0f, vmin = 2.0f;
        int bqmax = cc * 8, bqmin = cc * 8;

        #pragma unroll
        for (int c = 0; c < 8; c++) {
            const int q = cc * 8 + c;
            if (q < 15) {                  // software-pipelined prefetch of next chunk
                const int a = A0(q + 1);
                #pragma unroll
                for (int it = 0; it < 4; it++) nxt[it] = __ldcs(base + a + it * (2 * ROW_F4));
            }
            // 16-value max/min trees over the current chunk
            float mx0 = fmaxf(fmaxf(cur[0].x, cur[0].y), fmaxf(cur[0].z, cur[0].w));
            float mx1 = fmaxf(fmaxf(cur[1].x, cur[1].y), fmaxf(cur[1].z, cur[1].w));
            float mx2 = fmaxf(fmaxf(cur[2].x, cur[2].y), fmaxf(cur[2].z, cur[2].w));
            float mx3 = fmaxf(fmaxf(cur[3].x, cur[3].y), fmaxf(cur[3].z, cur[3].w));
            float cmax = fmaxf(fmaxf(mx0, mx1), fmaxf(mx2, mx3));
            float mn0 = fminf(fminf(cur[0].x, cur[0].y), fminf(cur[0].z, cur[0].w));
            float mn1 = fminf(fminf(cur[1].x, cur[1].y), fminf(cur[1].z, cur[1].w));
            float mn2 = fminf(fminf(cur[2].x, cur[2].y), fminf(cur[2].z, cur[2].w));
            float mn3 = fminf(fminf(cur[3].x, cur[3].y), fminf(cur[3].z, cur[3].w));
            float cmin = fminf(fminf(mn0, mn1), fminf(mn2, mn3));
            // Chunk-granular deferred tracking. Strict compare keeps the FIRST
            // chunk achieving the extremum (chunks ascend in flat index).
            if (cmax > vmax) { vmax = cmax; bqmax = q; }
            if (cmin < vmin) { vmin = cmin; bqmin = q; }
            if (q < 15) {
                #pragma unroll
                for (int it = 0; it < 4; it++) cur[it] = nxt[it];
            }
        }

        // Warp reduce values.
        float wmax = vmax, wmin = vmin;
        #pragma unroll
        for (int off = 16; off; off >>= 1) {
            wmax = fmaxf(wmax, __shfl_xor_sync(0xffffffffu, wmax, off));
            wmin = fminf(wmin, __shfl_xor_sync(0xffffffffu, wmin, off));
        }

        // Deferred index resolution: matching lanes re-load their best chunk
        // (64B each, L2-resident) and scan 16 values DESCENDING so overwrite
        // keeps the smallest flat index (reference first-occurrence semantics).
        unsigned candMax = 0xffffffffu, candMin = 0xffffffffu;
        if (vmax == wmax) {
            const int q = bqmax;
            const int a = A0(q);
            const int row0 = cy * 64 + (q & 7) * 8 + rsub;
            const int col  = ((2 * w + (q >> 3)) * 16 + csub) * 4;
            #pragma unroll
            for (int it = 3; it >= 0; it--) {
                float4 v = __ldcg(base + a + it * (2 * ROW_F4));
                unsigned i0 = (unsigned)((row0 + it * 2) * W_DIM + col);
                if (v.w == wmax) candMax = i0 + 3;
                if (v.z == wmax) candMax = i0 + 2;
                if (v.y == wmax) candMax = i0 + 1;
                if (v.x == wmax) candMax = i0;
            }
        }
        if (vmin == wmin) {
            const int q = bqmin;
            const int a = A0(q);
            const int row0 = cy * 64 + (q & 7) * 8 + rsub;
            const int col  = ((2 * w + (q >> 3)) * 16 + csub) * 4;
            #pragma unroll
            for (int it = 3; it >= 0; it--) {
                float4 v = __ldcg(base + a + it * (2 * ROW_F4));
                unsigned i0 = (unsigned)((row0 + it * 2) * W_DIM + col);
                if (v.w == wmin) candMin = i0 + 3;
                if (v.z == wmin) candMin = i0 + 2;
                if (v.y == wmin) candMin = i0 + 1;
                if (v.x == wmin) candMin = i0;
            }
        }
        #pragma unroll
        for (int off = 16; off; off >>= 1) {
            candMax = min(candMax, __shfl_xor_sync(0xffffffffu, candMax, off));
            candMin = min(candMin, __shfl_xor_sync(0xffffffffu, candMin, off));
        }

        if (lane == 0) {
            const int cell = cy * 16 + 2 * w + cc;
            g_cmax[img * NCELLS + cell] =
                ((unsigned long long)__float_as_uint(wmax) << 32) | (unsigned)(~candMax);
            g_cmin[img * NCELLS + cell] =
                ((unsigned long long)__float_as_uint(wmin) << 32) | candMin;
        }
    }

    // ---------------- handoff: last of 16 blocks per image finalizes ----------------
    __threadfence();                        // every thread: push cell results to GPU scope
    __syncthreads();
    __shared__ int sLast;
    if (tid == 0) {
        unsigned prev = atomicAdd(&g_cnt[img], 1u);
        int last = (prev == 15);
        if (last) g_cnt[img] = 0;           // self-reset for next graph replay
        sLast = last;
    }
    __syncthreads();
    if (!sLast) return;
    __threadfence();                        // acquire side

    // ---------------- Phase 2: finalize (one block per image) ----------------
    const int t = img / C_DIM;
    const float sx = (float)ori[t * 2 + 1] / (float)W_DIM;
    const float sy = (float)ori[t * 2 + 0] / (float)H_DIM;

    __shared__ unsigned long long key[NCELLS];
    __shared__ unsigned long long sG[16];   // [0:8) img-max partials, [8:16) img-min partials

    unsigned long long pM = __ldcg(&g_cmax[img * NCELLS + tid]);
    unsigned long long pN = __ldcg(&g_cmin[img * NCELLS + tid]);
    unsigned bits = (unsigned)(pM >> 32);
    unsigned pidx = ~(unsigned)(pM & 0xffffffffull);
    bool valid = __uint_as_float(bits) > THRESH;   // fg cell iff its max exceeds threshold

    // Unique sort key: descending score, ascending cell id; invalid cells last (stable by cid).
    unsigned long long k = valid ? ((pM & 0xFFFFFFFF00000000ULL) | (unsigned)(255 - tid))
                                 : (unsigned long long)(unsigned)(255 - tid);
    key[tid] = k;

    // Image-global extrema.
    unsigned long long gm = pM, gn = pN;
    #pragma unroll
    for (int off = 16; off; off >>= 1) {
        gm = umaxll(gm, __shfl_xor_sync(0xffffffffu, gm, off));
        gn = uminll(gn, __shfl_xor_sync(0xffffffffu, gn, off));
    }
    if (lane == 0) { sG[w] = gm; sG[8 + w] = gn; }

    int nvalid = __syncthreads_count((int)valid);

    int rank = 0;
    #pragma unroll 8
    for (int j = 0; j < NCELLS; j++) rank += (key[j] > k) ? 1 : 0;

    bool any_fg  = (nvalid > 0);
    int fg_count = any_fg ? (nvalid < NUM_FG ? nvalid : NUM_FG) : 1;

    float* o = out + (size_t)img * MAX_PTS * 4;
    if (tid < MAX_PTS * 4) o[tid] = 0.0f;   // 168 < 256: full zero of this image's block
    __syncthreads();

    if (any_fg) {
        if (rank < NUM_FG && valid) {
            float s  = __uint_as_float(bits);
            float px = (float)(pidx % W_DIM);
            float py = (float)(pidx / W_DIM);
            float* r = o + rank * 4;
            r[0] = px * sx; r[1] = py * sy; r[2] = s; r[3] = 1.0f;
        }
    } else if (tid == 0) {
        unsigned long long m = sG[0];
        #pragma unroll
        for (int i = 1; i < 8; i++) m = umaxll(m, sG[i]);
        unsigned gb = (unsigned)(m >> 32);
        unsigned gi = ~(unsigned)(m & 0xffffffffull);
        o[0] = (float)(gi % W_DIM) * sx;
        o[1] = (float)(gi / W_DIM) * sy;
        o[2] = __uint_as_float(gb);
        o[3] = 1.0f;
    }

    if (tid == 0) {
        unsigned long long n = sG[8];
        #pragma unroll
        for (int i = 1; i < 8; i++) n = uminll(n, sG[8 + i]);
        unsigned bb = (unsigned)(n >> 32);
        unsigned bi = (unsigned)(n & 0xffffffffull);
        float* r = o + fg_count * 4;
        r[0] = (float)(bi % W_DIM) * sx;
        r[1] = (float)(bi / W_DIM) * sy;
        r[2] = __uint_as_float(bb);
        r[3] = 0.0f;
        if (write_nums) {
            float* nums = out + (size_t)NIMG * MAX_PTS * 4;
            nums[img] = (float)(fg_count + NUM_BG);
        }
    }
}

extern "C" void kernel_launch(void* const* d_in, const int* in_sizes, int n_in,
                              void* d_out, int out_size) {
    const float* sim = (const float*)d_in[0];
    // d_in[1] = category_ids (unused by the reference output)
    const int* ori = (const int*)d_in[2];

    int write_nums = (out_size >= NIMG * MAX_PTS * 4 + NIMG) ? 1 : 0;
    fused_kernel<<<NIMG * NGRID, 256>>>(sim, ori, (float*)d_out, write_nums);
}